// round 12
// baseline (speedup 1.0000x reference)
#include <cuda_runtime.h>
#include <cstdint>

#define THREADS 128
#define SPT 2
#define SPB (THREADS * SPT)   // 256 samples per block

// Packed fp32x2 ops (sm_103a, PTX-only)
#define FFMA2(D, A, B, C) \
    asm("fma.rn.f32x2 %0, %1, %2, %3;" : "=l"(D) : "l"(A), "l"(B), "l"(C))
#define ADD2(D, A, B) \
    asm("add.rn.f32x2 %0, %1, %2;" : "=l"(D) : "l"(A), "l"(B))
#define MUL2(D, A, B) \
    asm("mul.rn.f32x2 %0, %1, %2;" : "=l"(D) : "l"(A), "l"(B))
#define PACK2(D, LO, HI) \
    asm("mov.b64 %0, {%1, %2};" : "=l"(D) : "f"(LO), "f"(HI))
#define UNPACK2(LO, HI, S) \
    asm("mov.b64 {%0, %1}, %2;" : "=f"(LO), "=f"(HI) : "l"(S))

__device__ __forceinline__ uint64_t fabs2(uint64_t v) {
    return v & 0x7FFFFFFF7FFFFFFFULL;      // 2x LOP3, alu pipe
}

// Doubled-scale packed node: X' = (X1+X2) + wq*|X1-X2|, wq = 1-2w (packed dup).
__device__ __forceinline__ uint64_t pnode(uint64_t x1, uint64_t x2, uint64_t wq,
                                          uint64_t NEG1) {
    uint64_t s, d, o;
    ADD2(s, x1, x2);
    FFMA2(d, x2, NEG1, x1);                // x1 - x2
    uint64_t ad = fabs2(d);
    FFMA2(o, wq, ad, s);
    return o;
}

__global__ void __launch_bounds__(THREADS)
bacon_forest_kernel(const float* __restrict__ c20,
                    const float* __restrict__ w_raw,
                    float* __restrict__ out,
                    int B)
{
    // Per-tree weights as (1-2*sigmoid), DUPLICATED into float2.
    // Row = 20 float2 = 160B: [0..9]=layer0, [10..18]=upper, [19]=pad.
    __shared__ __align__(16) float2 wpack[19 * 20];
    // One buffer, two lives: input stage (SPB*20), then output stage (SPB*19).
    __shared__ __align__(16) float buf[SPB * 20];

    const int tid = threadIdx.x;

    for (int i = tid; i < 19 * 19; i += THREADS) {
        int r = i / 19;
        int c = i - r * 19;
        float raw = __ldg(&w_raw[i]);
        float sig = 1.0f / (1.0f + __expf(-raw));
        float wq  = fmaf(-2.0f, sig, 1.0f);         // 1 - 2w
        wpack[r * 20 + c] = make_float2(wq, wq);
    }
    for (int i = tid; i < 19; i += THREADS)
        wpack[i * 20 + 19] = make_float2(0.0f, 0.0f);

    const int base = blockIdx.x * SPB;
    const int nS   = min(SPB, B - base);

    // Coalesced input staging (block region contiguous, 16B-aligned).
    {
        const float4* g4 = reinterpret_cast<const float4*>(c20 + (size_t)base * 20);
        float4*       b4 = reinterpret_cast<float4*>(buf);
        const int nV = nS * 5;
        for (int i = tid; i < nV; i += THREADS)
            b4[i] = g4[i];
    }
    __syncthreads();

    // Tree-invariant packed pairs for samples (tid, tid+THREADS):
    // S2[j] = (a+b) both samples, AD2[j] = |a-b| both samples.
    uint64_t S2[10], AD2[10];
    {
        float sm[2][10], ad[2][10];
        #pragma unroll
        for (int s = 0; s < 2; ++s) {
            const float4* xp = reinterpret_cast<const float4*>(&buf[(tid + s * THREADS) * 20]);
            float4 q0 = xp[0], q1 = xp[1], q2 = xp[2], q3 = xp[3], q4 = xp[4];
            float x[20] = { q0.x, q0.y, q0.z, q0.w,  q1.x, q1.y, q1.z, q1.w,
                            q2.x, q2.y, q2.z, q2.w,  q3.x, q3.y, q3.z, q3.w,
                            q4.x, q4.y, q4.z, q4.w };
            #pragma unroll
            for (int j = 0; j < 10; ++j) {
                float a = x[2 * j], b = x[2 * j + 1];
                sm[s][j] = a + b;
                ad[s][j] = fabsf(a - b);
            }
        }
        #pragma unroll
        for (int j = 0; j < 10; ++j) {
            PACK2(S2[j],  sm[0][j], sm[1][j]);
            PACK2(AD2[j], ad[0][j], ad[1][j]);
        }
    }
    __syncthreads();    // input reads done before buf is reused for outputs

    const uint64_t NEG1 = 0xBF800000BF800000ULL;   // (-1.0f, -1.0f)
    const uint64_t FOUR = 0x4080000040800000ULL;   // ( 4.0f,  4.0f)

    #pragma unroll
    for (int t = 0; t < 19; ++t) {
        // Tree weights: 10x LDS.128 (uniform -> broadcast), packed dup u64s.
        const ulonglong2* wp = reinterpret_cast<const ulonglong2*>(&wpack[t * 20]);
        ulonglong2 W0 = wp[0], W1 = wp[1], W2 = wp[2], W3 = wp[3], W4 = wp[4];
        ulonglong2 W5 = wp[5], W6 = wp[6], W7 = wp[7], W8 = wp[8], W9 = wp[9];
        // layer0 wq: W0.x..W4.y (cols 0..9); upper: W5.x..W9.x (cols 10..18)

        // Layer 0 (20 -> 10), doubled scale: Y = S2 + wq*AD2  (one FFMA2 each)
        uint64_t Y0, Y1, Y2, Y3, Y4, Y5, Y6, Y7, Y8, Y9;
        FFMA2(Y0, W0.x, AD2[0], S2[0]);
        FFMA2(Y1, W0.y, AD2[1], S2[1]);
        FFMA2(Y2, W1.x, AD2[2], S2[2]);
        FFMA2(Y3, W1.y, AD2[3], S2[3]);
        FFMA2(Y4, W2.x, AD2[4], S2[4]);
        FFMA2(Y5, W2.y, AD2[5], S2[5]);
        FFMA2(Y6, W3.x, AD2[6], S2[6]);
        FFMA2(Y7, W3.y, AD2[7], S2[7]);
        FFMA2(Y8, W4.x, AD2[8], S2[8]);
        FFMA2(Y9, W4.y, AD2[9], S2[9]);

        // Layer 1 (10 -> 5): cols 10..14   (scale 4)
        uint64_t Z0 = pnode(Y0, Y1, W5.x, NEG1);
        uint64_t Z1 = pnode(Y2, Y3, W5.y, NEG1);
        uint64_t Z2 = pnode(Y4, Y5, W6.x, NEG1);
        uint64_t Z3 = pnode(Y6, Y7, W6.y, NEG1);
        uint64_t Z4 = pnode(Y8, Y9, W7.x, NEG1);

        // Layer 2 (5 -> 2, carry Z4): cols 15,16   (scale 8)
        uint64_t V0 = pnode(Z0, Z1, W7.y, NEG1);
        uint64_t V1 = pnode(Z2, Z3, W8.x, NEG1);

        // Layer 3 (3 -> 1, carry Z4): col 17   (scale 16)
        uint64_t R0 = pnode(V0, V1, W8.y, NEG1);

        // Layer 4 (2 -> 1): col 18. Rescale carry Z4 (scale 4 -> 16, exact).
        uint64_t Z4s;
        MUL2(Z4s, Z4, FOUR);
        uint64_t O = pnode(R0, Z4s, W9.x, NEG1);   // scale 32

        // Tail: unpack once, exact /32, clip with reference constants.
        float o0, o1;
        UNPACK2(o0, o1, O);
        o0 = fminf(fmaxf(o0 * 0.03125f, 1e-6f), 1.0f - 1e-6f);
        o1 = fminf(fmaxf(o1 * 0.03125f, 1e-6f), 1.0f - 1e-6f);
        buf[tid * 19 + t]             = o0;   // stride 19: conflict-free
        buf[(tid + THREADS) * 19 + t] = o1;
    }
    __syncthreads();

    // Coalesced writeback of nS*19 floats (base*19 is 16B-aligned).
    const int nFlt = nS * 19;
    const int nVec = nFlt >> 2;
    float*        og = out + (size_t)base * 19;
    float4*       o4 = reinterpret_cast<float4*>(og);
    const float4* s4 = reinterpret_cast<const float4*>(buf);

    for (int i = tid; i < nVec; i += THREADS)
        o4[i] = s4[i];
    for (int i = (nVec << 2) + tid; i < nFlt; i += THREADS)
        og[i] = buf[i];
}

extern "C" void kernel_launch(void* const* d_in, const int* in_sizes, int n_in,
                              void* d_out, int out_size) {
    // metadata order: p1 (int32), p2 (int32), c20 (float32, B*20), w_raw (float32, 361)
    const float* c20   = (const float*)d_in[2];
    const float* w_raw = (const float*)d_in[3];
    float* out = (float*)d_out;
    int B = in_sizes[2] / 20;
    int grid = (B + SPB - 1) / SPB;
    bacon_forest_kernel<<<grid, THREADS>>>(c20, w_raw, out, B);
}

// round 13
// speedup vs baseline: 1.0006x; 1.0006x over previous
#include <cuda_runtime.h>
#include <cstdint>

#define THREADS 128
#define SPT 2
#define SPB (THREADS * SPT)   // 256 samples per block

// Packed fp32x2 ops (sm_103a, PTX-only)
#define FFMA2(D, A, B, C) \
    asm("fma.rn.f32x2 %0, %1, %2, %3;" : "=l"(D) : "l"(A), "l"(B), "l"(C))
#define ADD2(D, A, B) \
    asm("add.rn.f32x2 %0, %1, %2;" : "=l"(D) : "l"(A), "l"(B))
#define MUL2(D, A, B) \
    asm("mul.rn.f32x2 %0, %1, %2;" : "=l"(D) : "l"(A), "l"(B))
#define PACK2(D, LO, HI) \
    asm("mov.b64 %0, {%1, %2};" : "=l"(D) : "f"(LO), "f"(HI))
#define UNPACK2(LO, HI, S) \
    asm("mov.b64 {%0, %1}, %2;" : "=f"(LO), "=f"(HI) : "l"(S))

__device__ __forceinline__ uint64_t fabs2(uint64_t v) {
    return v & 0x7FFFFFFF7FFFFFFFULL;      // 2x LOP3, alu pipe
}

// Doubled-scale packed node: X' = (X1+X2) + wq*|X1-X2|, wq = 1-2w (packed dup).
__device__ __forceinline__ uint64_t pnode(uint64_t x1, uint64_t x2, uint64_t wq,
                                          uint64_t NEG1) {
    uint64_t s, d, o;
    ADD2(s, x1, x2);
    FFMA2(d, x2, NEG1, x1);                // x1 - x2
    uint64_t ad = fabs2(d);
    FFMA2(o, wq, ad, s);
    return o;
}

__global__ void __launch_bounds__(THREADS, 8)   // cap 64 regs -> 32 warps/SM
bacon_forest_kernel(const float* __restrict__ c20,
                    const float* __restrict__ w_raw,
                    float* __restrict__ out,
                    int B)
{
    // Per-tree weights as (1-2*sigmoid), DUPLICATED into float2.
    // Row = 20 float2 = 160B: [0..9]=layer0, [10..18]=upper, [19]=pad.
    __shared__ __align__(16) float2 wpack[19 * 20];
    // One buffer, two lives: input stage (SPB*20), then output stage (SPB*19).
    __shared__ __align__(16) float buf[SPB * 20];

    const int tid = threadIdx.x;

    for (int i = tid; i < 19 * 19; i += THREADS) {
        int r = i / 19;
        int c = i - r * 19;
        float raw = __ldg(&w_raw[i]);
        float sig = 1.0f / (1.0f + __expf(-raw));
        float wq  = fmaf(-2.0f, sig, 1.0f);         // 1 - 2w
        wpack[r * 20 + c] = make_float2(wq, wq);
    }
    for (int i = tid; i < 19; i += THREADS)
        wpack[i * 20 + 19] = make_float2(0.0f, 0.0f);

    const int base = blockIdx.x * SPB;
    const int nS   = min(SPB, B - base);

    // Coalesced input staging (block region contiguous, 16B-aligned).
    {
        const float4* g4 = reinterpret_cast<const float4*>(c20 + (size_t)base * 20);
        float4*       b4 = reinterpret_cast<float4*>(buf);
        const int nV = nS * 5;
        for (int i = tid; i < nV; i += THREADS)
            b4[i] = g4[i];
    }
    __syncthreads();

    // Tree-invariant packed pairs for samples (tid, tid+THREADS):
    // S2[j] = (a+b) both samples, AD2[j] = |a-b| both samples.
    uint64_t S2[10], AD2[10];
    {
        float sm[2][10], ad[2][10];
        #pragma unroll
        for (int s = 0; s < 2; ++s) {
            const float4* xp = reinterpret_cast<const float4*>(&buf[(tid + s * THREADS) * 20]);
            float4 q0 = xp[0], q1 = xp[1], q2 = xp[2], q3 = xp[3], q4 = xp[4];
            float x[20] = { q0.x, q0.y, q0.z, q0.w,  q1.x, q1.y, q1.z, q1.w,
                            q2.x, q2.y, q2.z, q2.w,  q3.x, q3.y, q3.z, q3.w,
                            q4.x, q4.y, q4.z, q4.w };
            #pragma unroll
            for (int j = 0; j < 10; ++j) {
                float a = x[2 * j], b = x[2 * j + 1];
                sm[s][j] = a + b;
                ad[s][j] = fabsf(a - b);
            }
        }
        #pragma unroll
        for (int j = 0; j < 10; ++j) {
            PACK2(S2[j],  sm[0][j], sm[1][j]);
            PACK2(AD2[j], ad[0][j], ad[1][j]);
        }
    }
    __syncthreads();    // input reads done before buf is reused for outputs

    const uint64_t NEG1   = 0xBF800000BF800000ULL;   // (-1.0f, -1.0f)
    const uint64_t FOUR   = 0x4080000040800000ULL;   // ( 4.0f,  4.0f)
    const uint64_t INV32  = 0x3D0000003D000000ULL;   // (1/32, 1/32)

    #pragma unroll
    for (int t = 0; t < 19; ++t) {
        // Tree weights: 10x LDS.128 (uniform -> broadcast), packed dup u64s.
        const ulonglong2* wp = reinterpret_cast<const ulonglong2*>(&wpack[t * 20]);
        ulonglong2 W0 = wp[0], W1 = wp[1], W2 = wp[2], W3 = wp[3], W4 = wp[4];
        ulonglong2 W5 = wp[5], W6 = wp[6], W7 = wp[7], W8 = wp[8], W9 = wp[9];
        // layer0 wq: W0.x..W4.y (cols 0..9); upper: W5.x..W9.x (cols 10..18)

        // Layer 0 (20 -> 10), doubled scale: Y = S2 + wq*AD2  (one FFMA2 each)
        uint64_t Y0, Y1, Y2, Y3, Y4, Y5, Y6, Y7, Y8, Y9;
        FFMA2(Y0, W0.x, AD2[0], S2[0]);
        FFMA2(Y1, W0.y, AD2[1], S2[1]);
        FFMA2(Y2, W1.x, AD2[2], S2[2]);
        FFMA2(Y3, W1.y, AD2[3], S2[3]);
        FFMA2(Y4, W2.x, AD2[4], S2[4]);
        FFMA2(Y5, W2.y, AD2[5], S2[5]);
        FFMA2(Y6, W3.x, AD2[6], S2[6]);
        FFMA2(Y7, W3.y, AD2[7], S2[7]);
        FFMA2(Y8, W4.x, AD2[8], S2[8]);
        FFMA2(Y9, W4.y, AD2[9], S2[9]);

        // Layer 1 (10 -> 5): cols 10..14   (scale 4)
        uint64_t Z0 = pnode(Y0, Y1, W5.x, NEG1);
        uint64_t Z1 = pnode(Y2, Y3, W5.y, NEG1);
        uint64_t Z2 = pnode(Y4, Y5, W6.x, NEG1);
        uint64_t Z3 = pnode(Y6, Y7, W6.y, NEG1);
        uint64_t Z4 = pnode(Y8, Y9, W7.x, NEG1);

        // Layer 2 (5 -> 2, carry Z4): cols 15,16   (scale 8)
        uint64_t V0 = pnode(Z0, Z1, W7.y, NEG1);
        uint64_t V1 = pnode(Z2, Z3, W8.x, NEG1);

        // Layer 3 (3 -> 1, carry Z4): col 17   (scale 16)
        uint64_t R0 = pnode(V0, V1, W8.y, NEG1);

        // Layer 4 (2 -> 1): col 18. Rescale carry Z4 (scale 4 -> 16, exact).
        uint64_t Z4s;
        MUL2(Z4s, Z4, FOUR);
        uint64_t O = pnode(R0, Z4s, W9.x, NEG1);   // scale 32

        // Tail: packed exact /32, then unpack + clip (no packed min/max in PTX).
        uint64_t Os;
        MUL2(Os, O, INV32);
        float o0, o1;
        UNPACK2(o0, o1, Os);
        o0 = fminf(fmaxf(o0, 1e-6f), 1.0f - 1e-6f);
        o1 = fminf(fmaxf(o1, 1e-6f), 1.0f - 1e-6f);
        buf[tid * 19 + t]             = o0;   // stride 19: conflict-free
        buf[(tid + THREADS) * 19 + t] = o1;
    }
    __syncthreads();

    // Coalesced writeback of nS*19 floats (base*19 is 16B-aligned).
    const int nFlt = nS * 19;
    const int nVec = nFlt >> 2;
    float*        og = out + (size_t)base * 19;
    float4*       o4 = reinterpret_cast<float4*>(og);
    const float4* s4 = reinterpret_cast<const float4*>(buf);

    for (int i = tid; i < nVec; i += THREADS)
        o4[i] = s4[i];
    for (int i = (nVec << 2) + tid; i < nFlt; i += THREADS)
        og[i] = buf[i];
}

extern "C" void kernel_launch(void* const* d_in, const int* in_sizes, int n_in,
                              void* d_out, int out_size) {
    // metadata order: p1 (int32), p2 (int32), c20 (float32, B*20), w_raw (float32, 361)
    const float* c20   = (const float*)d_in[2];
    const float* w_raw = (const float*)d_in[3];
    float* out = (float*)d_out;
    int B = in_sizes[2] / 20;
    int grid = (B + SPB - 1) / SPB;
    bacon_forest_kernel<<<grid, THREADS>>>(c20, w_raw, out, B);
}

// round 14
// speedup vs baseline: 1.1518x; 1.1511x over previous
#include <cuda_runtime.h>
#include <cstdint>

#define THREADS 128
#define SPT 2
#define SPB (THREADS * SPT)   // 256 samples per block

// Packed fp32x2 ops (sm_103a, PTX-only)
#define FFMA2(D, A, B, C) \
    asm("fma.rn.f32x2 %0, %1, %2, %3;" : "=l"(D) : "l"(A), "l"(B), "l"(C))
#define ADD2(D, A, B) \
    asm("add.rn.f32x2 %0, %1, %2;" : "=l"(D) : "l"(A), "l"(B))
#define MUL2(D, A, B) \
    asm("mul.rn.f32x2 %0, %1, %2;" : "=l"(D) : "l"(A), "l"(B))
#define PACK2(D, LO, HI) \
    asm("mov.b64 %0, {%1, %2};" : "=l"(D) : "f"(LO), "f"(HI))
#define UNPACK2(LO, HI, S) \
    asm("mov.b64 {%0, %1}, %2;" : "=f"(LO), "=f"(HI) : "l"(S))

// Transformed weights wq = 1-2*sigmoid(w_raw), duplicated (wq,wq).
// Row = 20 float2: [0..9]=layer0, [10..18]=upper, [19]=pad.
__constant__ float2 c_wp[19 * 20];
__device__   float2 g_wstage[19 * 20];   // staging for D2D memcpy into c_wp

__device__ __forceinline__ uint64_t fabs2(uint64_t v) {
    return v & 0x7FFFFFFF7FFFFFFFULL;      // 2x LOP3, alu pipe
}

// Doubled-scale packed node: X' = (X1+X2) + wq*|X1-X2|, wq = 1-2w (dup).
__device__ __forceinline__ uint64_t pnode(uint64_t x1, uint64_t x2, uint64_t wq,
                                          uint64_t NEG1) {
    uint64_t s, d, o;
    ADD2(s, x1, x2);
    FFMA2(d, x2, NEG1, x1);                // x1 - x2
    uint64_t ad = fabs2(d);
    FFMA2(o, wq, ad, s);
    return o;
}

// Prep kernel: sigmoid-transform weights into the staging global.
__global__ void bacon_prep_kernel(const float* __restrict__ w_raw) {
    int i = threadIdx.x;
    if (i < 19 * 19) {
        int r = i / 19;
        int c = i - r * 19;
        float sig = 1.0f / (1.0f + __expf(-w_raw[i]));
        float wq  = fmaf(-2.0f, sig, 1.0f);
        g_wstage[r * 20 + c] = make_float2(wq, wq);
    } else if (i < 19 * 19 + 19) {
        int r = i - 19 * 19;
        g_wstage[r * 20 + 19] = make_float2(0.0f, 0.0f);
    }
}

__global__ void __launch_bounds__(THREADS, 8)   // cap 64 regs
bacon_forest_kernel(const float* __restrict__ c20,
                    float* __restrict__ out,
                    int B)
{
    // One buffer, two lives: input stage (SPB*20), then output stage (SPB*19).
    __shared__ __align__(16) float buf[SPB * 20];

    const int tid  = threadIdx.x;
    const int base = blockIdx.x * SPB;
    const int nS   = min(SPB, B - base);

    // Coalesced input staging (block region contiguous, 16B-aligned).
    {
        const float4* g4 = reinterpret_cast<const float4*>(c20 + (size_t)base * 20);
        float4*       b4 = reinterpret_cast<float4*>(buf);
        const int nV = nS * 5;
        for (int i = tid; i < nV; i += THREADS)
            b4[i] = g4[i];
    }
    __syncthreads();

    // Tree-invariant packed pairs for samples (tid, tid+THREADS):
    // S2[j] = (a+b) both samples, AD2[j] = |a-b| both samples.
    uint64_t S2[10], AD2[10];
    {
        float sm[2][10], ad[2][10];
        #pragma unroll
        for (int s = 0; s < 2; ++s) {
            const float4* xp = reinterpret_cast<const float4*>(&buf[(tid + s * THREADS) * 20]);
            float4 q0 = xp[0], q1 = xp[1], q2 = xp[2], q3 = xp[3], q4 = xp[4];
            float x[20] = { q0.x, q0.y, q0.z, q0.w,  q1.x, q1.y, q1.z, q1.w,
                            q2.x, q2.y, q2.z, q2.w,  q3.x, q3.y, q3.z, q3.w,
                            q4.x, q4.y, q4.z, q4.w };
            #pragma unroll
            for (int j = 0; j < 10; ++j) {
                float a = x[2 * j], b = x[2 * j + 1];
                sm[s][j] = a + b;
                ad[s][j] = fabsf(a - b);
            }
        }
        #pragma unroll
        for (int j = 0; j < 10; ++j) {
            PACK2(S2[j],  sm[0][j], sm[1][j]);
            PACK2(AD2[j], ad[0][j], ad[1][j]);
        }
    }
    __syncthreads();    // input reads done before buf is reused for outputs

    const uint64_t NEG1   = 0xBF800000BF800000ULL;   // (-1.0f, -1.0f)
    const uint64_t FOUR   = 0x4080000040800000ULL;   // ( 4.0f,  4.0f)
    const uint64_t INV32  = 0x3D0000003D000000ULL;   // (1/32, 1/32)

    #pragma unroll
    for (int t = 0; t < 19; ++t) {
        // Tree weights from the CONSTANT bank (separate port, zero L1/crossbar
        // traffic; uniform addrs with immediate offsets -> LDC/LDCU).
        const uint64_t* wc = reinterpret_cast<const uint64_t*>(&c_wp[t * 20]);
        uint64_t W0 = wc[0], W1 = wc[1], W2 = wc[2], W3 = wc[3], W4 = wc[4];
        uint64_t W5 = wc[5], W6 = wc[6], W7 = wc[7], W8 = wc[8], W9 = wc[9];
        uint64_t U0 = wc[10], U1 = wc[11], U2 = wc[12], U3 = wc[13], U4 = wc[14];
        uint64_t U5 = wc[15], U6 = wc[16], U7 = wc[17], U8 = wc[18];

        // Layer 0 (20 -> 10), doubled scale: Y = S2 + wq*AD2  (one FFMA2 each)
        uint64_t Y0, Y1, Y2, Y3, Y4, Y5, Y6, Y7, Y8, Y9;
        FFMA2(Y0, W0, AD2[0], S2[0]);
        FFMA2(Y1, W1, AD2[1], S2[1]);
        FFMA2(Y2, W2, AD2[2], S2[2]);
        FFMA2(Y3, W3, AD2[3], S2[3]);
        FFMA2(Y4, W4, AD2[4], S2[4]);
        FFMA2(Y5, W5, AD2[5], S2[5]);
        FFMA2(Y6, W6, AD2[6], S2[6]);
        FFMA2(Y7, W7, AD2[7], S2[7]);
        FFMA2(Y8, W8, AD2[8], S2[8]);
        FFMA2(Y9, W9, AD2[9], S2[9]);

        // Layer 1 (10 -> 5): cols 10..14   (scale 4)
        uint64_t Z0 = pnode(Y0, Y1, U0, NEG1);
        uint64_t Z1 = pnode(Y2, Y3, U1, NEG1);
        uint64_t Z2 = pnode(Y4, Y5, U2, NEG1);
        uint64_t Z3 = pnode(Y6, Y7, U3, NEG1);
        uint64_t Z4 = pnode(Y8, Y9, U4, NEG1);

        // Layer 2 (5 -> 2, carry Z4): cols 15,16   (scale 8)
        uint64_t V0 = pnode(Z0, Z1, U5, NEG1);
        uint64_t V1 = pnode(Z2, Z3, U6, NEG1);

        // Layer 3 (3 -> 1, carry Z4): col 17   (scale 16)
        uint64_t R0 = pnode(V0, V1, U7, NEG1);

        // Layer 4 (2 -> 1): col 18. Rescale carry Z4 (scale 4 -> 16, exact).
        uint64_t Z4s;
        MUL2(Z4s, Z4, FOUR);
        uint64_t O = pnode(R0, Z4s, U8, NEG1);   // scale 32

        // Tail: packed exact /32, then unpack + clip.
        uint64_t Os;
        MUL2(Os, O, INV32);
        float o0, o1;
        UNPACK2(o0, o1, Os);
        o0 = fminf(fmaxf(o0, 1e-6f), 1.0f - 1e-6f);
        o1 = fminf(fmaxf(o1, 1e-6f), 1.0f - 1e-6f);
        buf[tid * 19 + t]             = o0;   // stride 19: conflict-free
        buf[(tid + THREADS) * 19 + t] = o1;
    }
    __syncthreads();

    // Coalesced writeback of nS*19 floats (base*19 is 16B-aligned).
    const int nFlt = nS * 19;
    const int nVec = nFlt >> 2;
    float*        og = out + (size_t)base * 19;
    float4*       o4 = reinterpret_cast<float4*>(og);
    const float4* s4 = reinterpret_cast<const float4*>(buf);

    for (int i = tid; i < nVec; i += THREADS)
        o4[i] = s4[i];
    for (int i = (nVec << 2) + tid; i < nFlt; i += THREADS)
        og[i] = buf[i];
}

extern "C" void kernel_launch(void* const* d_in, const int* in_sizes, int n_in,
                              void* d_out, int out_size) {
    // metadata order: p1 (int32), p2 (int32), c20 (float32, B*20), w_raw (float32, 361)
    const float* c20   = (const float*)d_in[2];
    const float* w_raw = (const float*)d_in[3];
    float* out = (float*)d_out;
    int B = in_sizes[2] / 20;

    // 1) transform weights into staging global
    bacon_prep_kernel<<<1, 384>>>(w_raw);

    // 2) D2D copy into the constant bank (capturable memcpy node;
    //    cudaGetSymbolAddress is a pure query, no stream work)
    void* dst = nullptr; void* src = nullptr;
    cudaGetSymbolAddress(&dst, c_wp);
    cudaGetSymbolAddress(&src, g_wstage);
    cudaMemcpyAsync(dst, src, sizeof(float2) * 19 * 20,
                    cudaMemcpyDeviceToDevice, 0);

    // 3) main kernel reads weights through the constant port
    int grid = (B + SPB - 1) / SPB;
    bacon_forest_kernel<<<grid, THREADS>>>(c20, out, B);
}

// round 15
// speedup vs baseline: 1.1882x; 1.0316x over previous
#include <cuda_runtime.h>
#include <cstdint>

#define THREADS 128
#define SPT 2
#define SPB (THREADS * SPT)   // 256 samples per block

// Packed fp32x2 ops (sm_103a, PTX-only)
#define FFMA2(D, A, B, C) \
    asm("fma.rn.f32x2 %0, %1, %2, %3;" : "=l"(D) : "l"(A), "l"(B), "l"(C))
#define ADD2(D, A, B) \
    asm("add.rn.f32x2 %0, %1, %2;" : "=l"(D) : "l"(A), "l"(B))
#define MUL2(D, A, B) \
    asm("mul.rn.f32x2 %0, %1, %2;" : "=l"(D) : "l"(A), "l"(B))
#define PACK2(D, LO, HI) \
    asm("mov.b64 %0, {%1, %2};" : "=l"(D) : "f"(LO), "f"(HI))
#define UNPACK2(LO, HI, S) \
    asm("mov.b64 {%0, %1}, %2;" : "=f"(LO), "=f"(HI) : "l"(S))

// Transformed weights wq = 1-2*sigmoid(w_raw), duplicated (wq,wq).
// Row = 20 float2: [0..9]=layer0, [10..18]=upper, [19]=pad.
__constant__ float2 c_wp[19 * 20];

__device__ __forceinline__ uint64_t fabs2(uint64_t v) {
    return v & 0x7FFFFFFF7FFFFFFFULL;      // 2x LOP3, alu pipe
}

// Doubled-scale packed node: X' = (X1+X2) + wq*|X1-X2|, wq = 1-2w (dup).
__device__ __forceinline__ uint64_t pnode(uint64_t x1, uint64_t x2, uint64_t wq,
                                          uint64_t NEG1) {
    uint64_t s, d, o;
    ADD2(s, x1, x2);
    FFMA2(d, x2, NEG1, x1);                // x1 - x2
    uint64_t ad = fabs2(d);
    FFMA2(o, wq, ad, s);
    return o;
}

// Prep kernel: sigmoid-transform weights, writing DIRECTLY into the memory
// backing c_wp (pointer from cudaGetSymbolAddress). The constant cache is
// invalidated at kernel-launch boundaries, so the next graph node (main
// kernel) reads fresh values through the const port. Removes the D2D
// memcpy node (~3us of graph-replay overhead).
__global__ void bacon_prep_kernel(const float* __restrict__ w_raw,
                                  float2* __restrict__ wdst) {
    int i = threadIdx.x;
    if (i < 19 * 19) {
        int r = i / 19;
        int c = i - r * 19;
        float sig = 1.0f / (1.0f + __expf(-w_raw[i]));
        float wq  = fmaf(-2.0f, sig, 1.0f);
        wdst[r * 20 + c] = make_float2(wq, wq);
    } else if (i < 19 * 19 + 19) {
        int r = i - 19 * 19;
        wdst[r * 20 + 19] = make_float2(0.0f, 0.0f);
    }
}

__global__ void __launch_bounds__(THREADS, 8)   // cap 64 regs
bacon_forest_kernel(const float* __restrict__ c20,
                    float* __restrict__ out,
                    int B)
{
    // One buffer, two lives: input stage (SPB*20), then output stage (SPB*19).
    __shared__ __align__(16) float buf[SPB * 20];

    const int tid  = threadIdx.x;
    const int base = blockIdx.x * SPB;
    const int nS   = min(SPB, B - base);

    // Coalesced input staging (block region contiguous, 16B-aligned).
    {
        const float4* g4 = reinterpret_cast<const float4*>(c20 + (size_t)base * 20);
        float4*       b4 = reinterpret_cast<float4*>(buf);
        const int nV = nS * 5;
        for (int i = tid; i < nV; i += THREADS)
            b4[i] = g4[i];
    }
    __syncthreads();

    // Tree-invariant packed pairs for samples (tid, tid+THREADS):
    // S2[j] = (a+b) both samples, AD2[j] = |a-b| both samples.
    uint64_t S2[10], AD2[10];
    {
        float sm[2][10], ad[2][10];
        #pragma unroll
        for (int s = 0; s < 2; ++s) {
            const float4* xp = reinterpret_cast<const float4*>(&buf[(tid + s * THREADS) * 20]);
            float4 q0 = xp[0], q1 = xp[1], q2 = xp[2], q3 = xp[3], q4 = xp[4];
            float x[20] = { q0.x, q0.y, q0.z, q0.w,  q1.x, q1.y, q1.z, q1.w,
                            q2.x, q2.y, q2.z, q2.w,  q3.x, q3.y, q3.z, q3.w,
                            q4.x, q4.y, q4.z, q4.w };
            #pragma unroll
            for (int j = 0; j < 10; ++j) {
                float a = x[2 * j], b = x[2 * j + 1];
                sm[s][j] = a + b;
                ad[s][j] = fabsf(a - b);
            }
        }
        #pragma unroll
        for (int j = 0; j < 10; ++j) {
            PACK2(S2[j],  sm[0][j], sm[1][j]);
            PACK2(AD2[j], ad[0][j], ad[1][j]);
        }
    }
    __syncthreads();    // input reads done before buf is reused for outputs

    const uint64_t NEG1   = 0xBF800000BF800000ULL;   // (-1.0f, -1.0f)
    const uint64_t FOUR   = 0x4080000040800000ULL;   // ( 4.0f,  4.0f)
    const uint64_t INV32  = 0x3D0000003D000000ULL;   // (1/32, 1/32)

    // Pairs 8,9 feed ONLY Y8/Y9 -> Z4 -> layer 4 (needs scale 16 there).
    // Pre-scale their invariants by 4 (exact) once: kills 19 per-tree MUL2s.
    MUL2(S2[8],  S2[8],  FOUR);
    MUL2(S2[9],  S2[9],  FOUR);
    MUL2(AD2[8], AD2[8], FOUR);
    MUL2(AD2[9], AD2[9], FOUR);

    #pragma unroll
    for (int t = 0; t < 19; ++t) {
        // Tree weights from the CONSTANT bank (uniform path, zero L1 traffic).
        const uint64_t* wc = reinterpret_cast<const uint64_t*>(&c_wp[t * 20]);
        uint64_t W0 = wc[0], W1 = wc[1], W2 = wc[2], W3 = wc[3], W4 = wc[4];
        uint64_t W5 = wc[5], W6 = wc[6], W7 = wc[7], W8 = wc[8], W9 = wc[9];
        uint64_t U0 = wc[10], U1 = wc[11], U2 = wc[12], U3 = wc[13], U4 = wc[14];
        uint64_t U5 = wc[15], U6 = wc[16], U7 = wc[17], U8 = wc[18];

        // Layer 0 (20 -> 10), doubled scale: Y = S2 + wq*AD2  (one FFMA2 each)
        // Y8,Y9 are at scale 8 (inputs pre-scaled x4).
        uint64_t Y0, Y1, Y2, Y3, Y4, Y5, Y6, Y7, Y8, Y9;
        FFMA2(Y0, W0, AD2[0], S2[0]);
        FFMA2(Y1, W1, AD2[1], S2[1]);
        FFMA2(Y2, W2, AD2[2], S2[2]);
        FFMA2(Y3, W3, AD2[3], S2[3]);
        FFMA2(Y4, W4, AD2[4], S2[4]);
        FFMA2(Y5, W5, AD2[5], S2[5]);
        FFMA2(Y6, W6, AD2[6], S2[6]);
        FFMA2(Y7, W7, AD2[7], S2[7]);
        FFMA2(Y8, W8, AD2[8], S2[8]);
        FFMA2(Y9, W9, AD2[9], S2[9]);

        // Layer 1 (10 -> 5): cols 10..14. Z0..Z3 scale 4; Z4 scale 16.
        uint64_t Z0 = pnode(Y0, Y1, U0, NEG1);
        uint64_t Z1 = pnode(Y2, Y3, U1, NEG1);
        uint64_t Z2 = pnode(Y4, Y5, U2, NEG1);
        uint64_t Z3 = pnode(Y6, Y7, U3, NEG1);
        uint64_t Z4 = pnode(Y8, Y9, U4, NEG1);

        // Layer 2 (5 -> 2, carry Z4): cols 15,16   (scale 8)
        uint64_t V0 = pnode(Z0, Z1, U5, NEG1);
        uint64_t V1 = pnode(Z2, Z3, U6, NEG1);

        // Layer 3 (3 -> 1, carry Z4): col 17   (scale 16)
        uint64_t R0 = pnode(V0, V1, U7, NEG1);

        // Layer 4 (2 -> 1): col 18. Z4 already at scale 16.
        uint64_t O = pnode(R0, Z4, U8, NEG1);    // scale 32

        // Tail: packed exact /32, then unpack + clip.
        uint64_t Os;
        MUL2(Os, O, INV32);
        float o0, o1;
        UNPACK2(o0, o1, Os);
        o0 = fminf(fmaxf(o0, 1e-6f), 1.0f - 1e-6f);
        o1 = fminf(fmaxf(o1, 1e-6f), 1.0f - 1e-6f);
        buf[tid * 19 + t]             = o0;   // stride 19: conflict-free
        buf[(tid + THREADS) * 19 + t] = o1;
    }
    __syncthreads();

    // Coalesced writeback of nS*19 floats (base*19 is 16B-aligned).
    const int nFlt = nS * 19;
    const int nVec = nFlt >> 2;
    float*        og = out + (size_t)base * 19;
    float4*       o4 = reinterpret_cast<float4*>(og);
    const float4* s4 = reinterpret_cast<const float4*>(buf);

    for (int i = tid; i < nVec; i += THREADS)
        o4[i] = s4[i];
    for (int i = (nVec << 2) + tid; i < nFlt; i += THREADS)
        og[i] = buf[i];
}

extern "C" void kernel_launch(void* const* d_in, const int* in_sizes, int n_in,
                              void* d_out, int out_size) {
    // metadata order: p1 (int32), p2 (int32), c20 (float32, B*20), w_raw (float32, 361)
    const float* c20   = (const float*)d_in[2];
    const float* w_raw = (const float*)d_in[3];
    float* out = (float*)d_out;
    int B = in_sizes[2] / 20;

    // 1) transform weights, writing straight into c_wp's backing store
    //    (cudaGetSymbolAddress is a pure query — no stream work, capturable)
    void* wdst = nullptr;
    cudaGetSymbolAddress(&wdst, c_wp);
    bacon_prep_kernel<<<1, 384>>>(w_raw, (float2*)wdst);

    // 2) main kernel reads weights through the constant port
    int grid = (B + SPB - 1) / SPB;
    bacon_forest_kernel<<<grid, THREADS>>>(c20, out, B);
}

// round 16
// speedup vs baseline: 1.2402x; 1.0437x over previous
#include <cuda_runtime.h>
#include <cstdint>

#define THREADS 128
#define SPT 2
#define SPB (THREADS * SPT)   // 256 samples per block

// Packed fp32x2 ops (sm_103a, PTX-only)
#define FFMA2(D, A, B, C) \
    asm("fma.rn.f32x2 %0, %1, %2, %3;" : "=l"(D) : "l"(A), "l"(B), "l"(C))
#define ADD2(D, A, B) \
    asm("add.rn.f32x2 %0, %1, %2;" : "=l"(D) : "l"(A), "l"(B))
#define MUL2(D, A, B) \
    asm("mul.rn.f32x2 %0, %1, %2;" : "=l"(D) : "l"(A), "l"(B))
#define PACK2(D, LO, HI) \
    asm("mov.b64 %0, {%1, %2};" : "=l"(D) : "f"(LO), "f"(HI))
#define UNPACK2(LO, HI, S) \
    asm("mov.b64 {%0, %1}, %2;" : "=f"(LO), "=f"(HI) : "l"(S))

// Transformed weights wq = 1-2*sigmoid(w_raw), duplicated (wq,wq).
// Row = 20 float2: [0..9]=layer0, [10..18]=upper, [19]=pad.
__constant__ float2 c_wp[19 * 20];

__device__ __forceinline__ uint64_t fabs2(uint64_t v) {
    return v & 0x7FFFFFFF7FFFFFFFULL;      // 2x LOP3, alu pipe
}

// Doubled-scale packed node: X' = (X1+X2) + wq*|X1-X2|, wq = 1-2w (dup).
__device__ __forceinline__ uint64_t pnode(uint64_t x1, uint64_t x2, uint64_t wq,
                                          uint64_t NEG1) {
    uint64_t s, d, o;
    ADD2(s, x1, x2);
    FFMA2(d, x2, NEG1, x1);                // x1 - x2
    uint64_t ad = fabs2(d);
    FFMA2(o, wq, ad, s);
    return o;
}

// Prep kernel: sigmoid-transform weights directly into c_wp's backing store.
// Completion trigger (implicit at kernel end) releases PDL dependents with
// full memory visibility.
__global__ void bacon_prep_kernel(const float* __restrict__ w_raw,
                                  float2* __restrict__ wdst) {
    int i = threadIdx.x;
    if (i < 19 * 19) {
        int r = i / 19;
        int c = i - r * 19;
        float sig = 1.0f / (1.0f + __expf(-w_raw[i]));
        float wq  = fmaf(-2.0f, sig, 1.0f);
        wdst[r * 20 + c] = make_float2(wq, wq);
    } else if (i < 19 * 19 + 19) {
        int r = i - 19 * 19;
        wdst[r * 20 + 19] = make_float2(0.0f, 0.0f);
    }
}

__global__ void __launch_bounds__(THREADS, 8)   // cap 64 regs
bacon_forest_kernel(const float* __restrict__ c20,
                    float* __restrict__ out,
                    int B)
{
    // One buffer, two lives: input stage (SPB*20), then output stage (SPB*19).
    __shared__ __align__(16) float buf[SPB * 20];

    const int tid  = threadIdx.x;
    const int base = blockIdx.x * SPB;
    const int nS   = min(SPB, B - base);

    // ---- Prologue: weight-independent. Overlaps the prep kernel under PDL. ----

    // Coalesced input staging (block region contiguous, 16B-aligned).
    {
        const float4* g4 = reinterpret_cast<const float4*>(c20 + (size_t)base * 20);
        float4*       b4 = reinterpret_cast<float4*>(buf);
        const int nV = nS * 5;
        for (int i = tid; i < nV; i += THREADS)
            b4[i] = g4[i];
    }
    __syncthreads();

    // Tree-invariant packed pairs for samples (tid, tid+THREADS):
    // S2[j] = (a+b) both samples, AD2[j] = |a-b| both samples.
    uint64_t S2[10], AD2[10];
    {
        float sm[2][10], ad[2][10];
        #pragma unroll
        for (int s = 0; s < 2; ++s) {
            const float4* xp = reinterpret_cast<const float4*>(&buf[(tid + s * THREADS) * 20]);
            float4 q0 = xp[0], q1 = xp[1], q2 = xp[2], q3 = xp[3], q4 = xp[4];
            float x[20] = { q0.x, q0.y, q0.z, q0.w,  q1.x, q1.y, q1.z, q1.w,
                            q2.x, q2.y, q2.z, q2.w,  q3.x, q3.y, q3.z, q3.w,
                            q4.x, q4.y, q4.z, q4.w };
            #pragma unroll
            for (int j = 0; j < 10; ++j) {
                float a = x[2 * j], b = x[2 * j + 1];
                sm[s][j] = a + b;
                ad[s][j] = fabsf(a - b);
            }
        }
        #pragma unroll
        for (int j = 0; j < 10; ++j) {
            PACK2(S2[j],  sm[0][j], sm[1][j]);
            PACK2(AD2[j], ad[0][j], ad[1][j]);
        }
    }
    __syncthreads();    // input reads done before buf is reused for outputs

    const uint64_t NEG1   = 0xBF800000BF800000ULL;   // (-1.0f, -1.0f)
    const uint64_t FOUR   = 0x4080000040800000ULL;   // ( 4.0f,  4.0f)
    const uint64_t INV32  = 0x3D0000003D000000ULL;   // (1/32, 1/32)

    // Pairs 8,9 feed ONLY Y8/Y9 -> Z4 -> layer 4 (needs scale 16 there).
    MUL2(S2[8],  S2[8],  FOUR);
    MUL2(S2[9],  S2[9],  FOUR);
    MUL2(AD2[8], AD2[8], FOUR);
    MUL2(AD2[9], AD2[9], FOUR);

    // ---- PDL gate: weights must be ready beyond this point. ----
    // No-op if this grid wasn't launched as a programmatic dependent.
    asm volatile("griddepcontrol.wait;" ::: "memory");

    #pragma unroll
    for (int t = 0; t < 19; ++t) {
        // Tree weights from the CONSTANT bank (uniform path, zero L1 traffic).
        const uint64_t* wc = reinterpret_cast<const uint64_t*>(&c_wp[t * 20]);
        uint64_t W0 = wc[0], W1 = wc[1], W2 = wc[2], W3 = wc[3], W4 = wc[4];
        uint64_t W5 = wc[5], W6 = wc[6], W7 = wc[7], W8 = wc[8], W9 = wc[9];
        uint64_t U0 = wc[10], U1 = wc[11], U2 = wc[12], U3 = wc[13], U4 = wc[14];
        uint64_t U5 = wc[15], U6 = wc[16], U7 = wc[17], U8 = wc[18];

        // Layer 0 (20 -> 10), doubled scale: Y = S2 + wq*AD2  (one FFMA2 each)
        // Y8,Y9 at scale 8 (inputs pre-scaled x4).
        uint64_t Y0, Y1, Y2, Y3, Y4, Y5, Y6, Y7, Y8, Y9;
        FFMA2(Y0, W0, AD2[0], S2[0]);
        FFMA2(Y1, W1, AD2[1], S2[1]);
        FFMA2(Y2, W2, AD2[2], S2[2]);
        FFMA2(Y3, W3, AD2[3], S2[3]);
        FFMA2(Y4, W4, AD2[4], S2[4]);
        FFMA2(Y5, W5, AD2[5], S2[5]);
        FFMA2(Y6, W6, AD2[6], S2[6]);
        FFMA2(Y7, W7, AD2[7], S2[7]);
        FFMA2(Y8, W8, AD2[8], S2[8]);
        FFMA2(Y9, W9, AD2[9], S2[9]);

        // Layer 1 (10 -> 5): cols 10..14. Z0..Z3 scale 4; Z4 scale 16.
        uint64_t Z0 = pnode(Y0, Y1, U0, NEG1);
        uint64_t Z1 = pnode(Y2, Y3, U1, NEG1);
        uint64_t Z2 = pnode(Y4, Y5, U2, NEG1);
        uint64_t Z3 = pnode(Y6, Y7, U3, NEG1);
        uint64_t Z4 = pnode(Y8, Y9, U4, NEG1);

        // Layer 2 (5 -> 2, carry Z4): cols 15,16   (scale 8)
        uint64_t V0 = pnode(Z0, Z1, U5, NEG1);
        uint64_t V1 = pnode(Z2, Z3, U6, NEG1);

        // Layer 3 (3 -> 1, carry Z4): col 17   (scale 16)
        uint64_t R0 = pnode(V0, V1, U7, NEG1);

        // Layer 4 (2 -> 1): col 18. Z4 already at scale 16.
        uint64_t O = pnode(R0, Z4, U8, NEG1);    // scale 32

        // Tail: packed exact /32, then unpack + clip.
        uint64_t Os;
        MUL2(Os, O, INV32);
        float o0, o1;
        UNPACK2(o0, o1, Os);
        o0 = fminf(fmaxf(o0, 1e-6f), 1.0f - 1e-6f);
        o1 = fminf(fmaxf(o1, 1e-6f), 1.0f - 1e-6f);
        buf[tid * 19 + t]             = o0;   // stride 19: conflict-free
        buf[(tid + THREADS) * 19 + t] = o1;
    }
    __syncthreads();

    // Coalesced writeback of nS*19 floats (base*19 is 16B-aligned).
    const int nFlt = nS * 19;
    const int nVec = nFlt >> 2;
    float*        og = out + (size_t)base * 19;
    float4*       o4 = reinterpret_cast<float4*>(og);
    const float4* s4 = reinterpret_cast<const float4*>(buf);

    for (int i = tid; i < nVec; i += THREADS)
        o4[i] = s4[i];
    for (int i = (nVec << 2) + tid; i < nFlt; i += THREADS)
        og[i] = buf[i];
}

extern "C" void kernel_launch(void* const* d_in, const int* in_sizes, int n_in,
                              void* d_out, int out_size) {
    // metadata order: p1 (int32), p2 (int32), c20 (float32, B*20), w_raw (float32, 361)
    const float* c20   = (const float*)d_in[2];
    const float* w_raw = (const float*)d_in[3];
    float* out = (float*)d_out;
    int B = in_sizes[2] / 20;

    // 1) transform weights straight into c_wp's backing store
    void* wdst = nullptr;
    cudaGetSymbolAddress(&wdst, c_wp);
    bacon_prep_kernel<<<1, 384>>>(w_raw, (float2*)wdst);

    // 2) main kernel as a PROGRAMMATIC DEPENDENT of the prep kernel:
    //    it may begin its weight-independent prologue while prep is in
    //    flight; griddepcontrol.wait gates the weight reads.
    int grid = (B + SPB - 1) / SPB;

    cudaLaunchConfig_t cfg = {};
    cfg.gridDim  = dim3((unsigned)grid, 1, 1);
    cfg.blockDim = dim3(THREADS, 1, 1);
    cfg.dynamicSmemBytes = 0;
    cfg.stream = 0;
    cudaLaunchAttribute attr[1];
    attr[0].id = cudaLaunchAttributeProgrammaticStreamSerialization;
    attr[0].val.programmaticStreamSerializationAllowed = 1;
    cfg.attrs = attr;
    cfg.numAttrs = 1;

    cudaError_t e = cudaLaunchKernelEx(&cfg, bacon_forest_kernel, c20, out, B);
    if (e != cudaSuccess) {
        // Fallback: plain serialized launch (griddepcontrol.wait is a no-op
        // when the grid is not a programmatic dependent).
        (void)cudaGetLastError();
        bacon_forest_kernel<<<grid, THREADS>>>(c20, out, B);
    }
}

// round 17
// speedup vs baseline: 1.2970x; 1.0457x over previous
#include <cuda_runtime.h>
#include <cstdint>

#define THREADS 128
#define SPT 2
#define SPB (THREADS * SPT)   // 256 samples per block

// Packed fp32x2 ops (sm_103a, PTX-only)
#define FFMA2(D, A, B, C) \
    asm("fma.rn.f32x2 %0, %1, %2, %3;" : "=l"(D) : "l"(A), "l"(B), "l"(C))
#define ADD2(D, A, B) \
    asm("add.rn.f32x2 %0, %1, %2;" : "=l"(D) : "l"(A), "l"(B))
#define MUL2(D, A, B) \
    asm("mul.rn.f32x2 %0, %1, %2;" : "=l"(D) : "l"(A), "l"(B))
#define PACK2(D, LO, HI) \
    asm("mov.b64 %0, {%1, %2};" : "=l"(D) : "f"(LO), "f"(HI))
#define UNPACK2(LO, HI, S) \
    asm("mov.b64 {%0, %1}, %2;" : "=f"(LO), "=f"(HI) : "l"(S))

// Transformed weights wq = 1-2*sigmoid(w_raw), duplicated (wq,wq).
// Row = 20 float2: [0..9]=layer0, [10..18]=upper, [19]=pad.
__constant__ float2 c_wp[19 * 20];

__device__ __forceinline__ uint64_t fabs2(uint64_t v) {
    return v & 0x7FFFFFFF7FFFFFFFULL;      // 2x LOP3, alu pipe
}

// Packed soft node (scaled form): X' = (X1+X2) + wq*|X1-X2|.
__device__ __forceinline__ uint64_t pnode(uint64_t x1, uint64_t x2, uint64_t wq,
                                          uint64_t NEG1) {
    uint64_t s, d, o;
    ADD2(s, x1, x2);
    FFMA2(d, x2, NEG1, x1);                // x1 - x2
    uint64_t ad = fabs2(d);
    FFMA2(o, wq, ad, s);
    return o;
}

// Prep kernel: sigmoid-transform weights directly into c_wp's backing store,
// then RELEASE PDL DEPENDENTS EARLY (after a gpu-scope fence) instead of at
// kernel drain.
__global__ void bacon_prep_kernel(const float* __restrict__ w_raw,
                                  float2* __restrict__ wdst) {
    int i = threadIdx.x;
    if (i < 19 * 19) {
        int r = i / 19;
        int c = i - r * 19;
        float sig = 1.0f / (1.0f + __expf(-w_raw[i]));
        float wq  = fmaf(-2.0f, sig, 1.0f);
        wdst[r * 20 + c] = make_float2(wq, wq);
    } else if (i < 19 * 19 + 19) {
        int r = i - 19 * 19;
        wdst[r * 20 + 19] = make_float2(0.0f, 0.0f);
    }
    __syncthreads();                      // all STGs issued
    asm volatile("membar.gl;" ::: "memory");
    asm volatile("griddepcontrol.launch_dependents;" ::: "memory");
}

__global__ void __launch_bounds__(THREADS, 8)   // cap 64 regs
bacon_forest_kernel(const float* __restrict__ c20,
                    float* __restrict__ out,
                    int B)
{
    // One buffer, two lives: input stage (SPB*20), then output stage (SPB*19).
    __shared__ __align__(16) float buf[SPB * 20];

    const int tid  = threadIdx.x;
    const int base = blockIdx.x * SPB;
    const int nS   = min(SPB, B - base);

    // ---- Prologue: weight-independent. Overlaps the prep kernel under PDL. ----

    // Coalesced input staging; unrolled fast path for full blocks.
    {
        const float4* g4 = reinterpret_cast<const float4*>(c20 + (size_t)base * 20);
        float4*       b4 = reinterpret_cast<float4*>(buf);
        if (nS == SPB) {
            #pragma unroll
            for (int k = 0; k < SPB * 5 / THREADS; ++k)
                b4[k * THREADS + tid] = g4[k * THREADS + tid];
        } else {
            const int nV = nS * 5;
            for (int i = tid; i < nV; i += THREADS)
                b4[i] = g4[i];
        }
    }
    __syncthreads();

    // Tree-invariant packed pairs for samples (tid, tid+THREADS), PRE-SCALED:
    // pairs 0..7 by 1/32, pairs 8,9 by 4/32=1/8 (absorbs old x4 carry rescale
    // AND the final /32 -> final output lands at scale 1, clipped directly).
    uint64_t S2[10], AD2[10];
    {
        float sm[2][10], ad[2][10];
        #pragma unroll
        for (int s = 0; s < 2; ++s) {
            const float4* xp = reinterpret_cast<const float4*>(&buf[(tid + s * THREADS) * 20]);
            float4 q0 = xp[0], q1 = xp[1], q2 = xp[2], q3 = xp[3], q4 = xp[4];
            float x[20] = { q0.x, q0.y, q0.z, q0.w,  q1.x, q1.y, q1.z, q1.w,
                            q2.x, q2.y, q2.z, q2.w,  q3.x, q3.y, q3.z, q3.w,
                            q4.x, q4.y, q4.z, q4.w };
            #pragma unroll
            for (int j = 0; j < 10; ++j) {
                float a = x[2 * j], b = x[2 * j + 1];
                sm[s][j] = a + b;
                ad[s][j] = fabsf(a - b);
            }
        }
        #pragma unroll
        for (int j = 0; j < 10; ++j) {
            PACK2(S2[j],  sm[0][j], sm[1][j]);
            PACK2(AD2[j], ad[0][j], ad[1][j]);
        }
    }
    __syncthreads();    // input reads done before buf is reused for outputs

    const uint64_t NEG1   = 0xBF800000BF800000ULL;   // (-1.0f, -1.0f)
    const uint64_t INV32  = 0x3D0000003D000000ULL;   // (1/32, 1/32)
    const uint64_t EIGHTH = 0x3E0000003E000000ULL;   // (1/8,  1/8 )

    #pragma unroll
    for (int j = 0; j < 8; ++j) {
        MUL2(S2[j],  S2[j],  INV32);
        MUL2(AD2[j], AD2[j], INV32);
    }
    #pragma unroll
    for (int j = 8; j < 10; ++j) {
        MUL2(S2[j],  S2[j],  EIGHTH);
        MUL2(AD2[j], AD2[j], EIGHTH);
    }

    // ---- PDL gate: weights must be ready beyond this point. ----
    asm volatile("griddepcontrol.wait;" ::: "memory");

    #pragma unroll
    for (int t = 0; t < 19; ++t) {
        // Tree weights from the CONSTANT bank (uniform path, zero L1 traffic).
        const uint64_t* wc = reinterpret_cast<const uint64_t*>(&c_wp[t * 20]);
        uint64_t W0 = wc[0], W1 = wc[1], W2 = wc[2], W3 = wc[3], W4 = wc[4];
        uint64_t W5 = wc[5], W6 = wc[6], W7 = wc[7], W8 = wc[8], W9 = wc[9];
        uint64_t U0 = wc[10], U1 = wc[11], U2 = wc[12], U3 = wc[13], U4 = wc[14];
        uint64_t U5 = wc[15], U6 = wc[16], U7 = wc[17], U8 = wc[18];

        // Layer 0 (20 -> 10): one FFMA2 per node (invariants pre-scaled).
        uint64_t Y0, Y1, Y2, Y3, Y4, Y5, Y6, Y7, Y8, Y9;
        FFMA2(Y0, W0, AD2[0], S2[0]);
        FFMA2(Y1, W1, AD2[1], S2[1]);
        FFMA2(Y2, W2, AD2[2], S2[2]);
        FFMA2(Y3, W3, AD2[3], S2[3]);
        FFMA2(Y4, W4, AD2[4], S2[4]);
        FFMA2(Y5, W5, AD2[5], S2[5]);
        FFMA2(Y6, W6, AD2[6], S2[6]);
        FFMA2(Y7, W7, AD2[7], S2[7]);
        FFMA2(Y8, W8, AD2[8], S2[8]);
        FFMA2(Y9, W9, AD2[9], S2[9]);

        // Layer 1 (10 -> 5): cols 10..14
        uint64_t Z0 = pnode(Y0, Y1, U0, NEG1);
        uint64_t Z1 = pnode(Y2, Y3, U1, NEG1);
        uint64_t Z2 = pnode(Y4, Y5, U2, NEG1);
        uint64_t Z3 = pnode(Y6, Y7, U3, NEG1);
        uint64_t Z4 = pnode(Y8, Y9, U4, NEG1);

        // Layer 2 (5 -> 2, carry Z4): cols 15,16
        uint64_t V0 = pnode(Z0, Z1, U5, NEG1);
        uint64_t V1 = pnode(Z2, Z3, U6, NEG1);

        // Layer 3 (3 -> 1, carry Z4): col 17
        uint64_t R0 = pnode(V0, V1, U7, NEG1);

        // Layer 4 (2 -> 1): col 18. Output already at scale 1.
        uint64_t O = pnode(R0, Z4, U8, NEG1);

        // Tail: unpack + clip (no packed fp min/max in PTX).
        float o0, o1;
        UNPACK2(o0, o1, O);
        o0 = fminf(fmaxf(o0, 1e-6f), 1.0f - 1e-6f);
        o1 = fminf(fmaxf(o1, 1e-6f), 1.0f - 1e-6f);
        buf[tid * 19 + t]             = o0;   // stride 19: conflict-free
        buf[(tid + THREADS) * 19 + t] = o1;
    }
    __syncthreads();

    // Coalesced writeback; unrolled fast path for full blocks.
    float*        og = out + (size_t)base * 19;
    float4*       o4 = reinterpret_cast<float4*>(og);
    const float4* s4 = reinterpret_cast<const float4*>(buf);
    if (nS == SPB) {
        // SPB*19 = 4864 floats = 1216 float4 = 9.5 per thread.
        #pragma unroll
        for (int k = 0; k < 9; ++k)
            o4[k * THREADS + tid] = s4[k * THREADS + tid];
        if (tid < (SPB * 19 / 4) - 9 * THREADS)                  // 64 leftovers
            o4[9 * THREADS + tid] = s4[9 * THREADS + tid];
    } else {
        const int nFlt = nS * 19;
        const int nVec = nFlt >> 2;
        for (int i = tid; i < nVec; i += THREADS)
            o4[i] = s4[i];
        for (int i = (nVec << 2) + tid; i < nFlt; i += THREADS)
            og[i] = buf[i];
    }
}

extern "C" void kernel_launch(void* const* d_in, const int* in_sizes, int n_in,
                              void* d_out, int out_size) {
    // metadata order: p1 (int32), p2 (int32), c20 (float32, B*20), w_raw (float32, 361)
    const float* c20   = (const float*)d_in[2];
    const float* w_raw = (const float*)d_in[3];
    float* out = (float*)d_out;
    int B = in_sizes[2] / 20;

    // 1) transform weights straight into c_wp's backing store
    void* wdst = nullptr;
    cudaGetSymbolAddress(&wdst, c_wp);
    bacon_prep_kernel<<<1, 384>>>(w_raw, (float2*)wdst);

    // 2) main kernel as PROGRAMMATIC DEPENDENT: prologue overlaps prep;
    //    griddepcontrol.wait gates the weight reads (released early by prep).
    int grid = (B + SPB - 1) / SPB;

    cudaLaunchConfig_t cfg = {};
    cfg.gridDim  = dim3((unsigned)grid, 1, 1);
    cfg.blockDim = dim3(THREADS, 1, 1);
    cfg.dynamicSmemBytes = 0;
    cfg.stream = 0;
    cudaLaunchAttribute attr[1];
    attr[0].id = cudaLaunchAttributeProgrammaticStreamSerialization;
    attr[0].val.programmaticStreamSerializationAllowed = 1;
    cfg.attrs = attr;
    cfg.numAttrs = 1;

    cudaError_t e = cudaLaunchKernelEx(&cfg, bacon_forest_kernel, c20, out, B);
    if (e != cudaSuccess) {
        (void)cudaGetLastError();
        bacon_forest_kernel<<<grid, THREADS>>>(c20, out, B);
    }
}